// round 2
// baseline (speedup 1.0000x reference)
#include <cuda_runtime.h>

// EfficientPWL, intercept form: out = x * a[i1] + b[i1]
// where a[i1] = slopes[c, i1], b[i1] = cumbias[c, i2] - cp[i2] * slopes[c, i1],
// i2 = max(i1-1, 0), uniform breakpoints linspace(-1,1,33), dt = 1/16.
// Valid because the PWL is continuous at every breakpoint.
//
// B=32, C=128, T=8192. One block per (b,c) row.

#define BATCH   32
#define CCH     128
#define TLEN    8192
#define NCP     33      // breakpoints / cumbias entries
#define NSL     34      // slopes per channel (also table size)
#define THREADS 256
#define VPT     8       // float4 per thread

__global__ void __launch_bounds__(THREADS)
efficient_pwl_kernel(const float* __restrict__ x,
                     const float* __restrict__ slopes,
                     const float* __restrict__ biases,
                     float* __restrict__ out) {
    __shared__ float  s_slope[NSL];
    __shared__ float  s_cumb[NCP];
    __shared__ float2 s_tab[NSL];   // (a, b) per bucket index i1

    const int row = blockIdx.x;          // b*C + c
    const int c   = row & (CCH - 1);
    const int tid = threadIdx.x;

    if (tid < NSL)
        s_slope[tid] = slopes[c * NSL + tid];
    __syncthreads();

    if (tid == 0) {
        const float dt = 0.0625f;
        float acc = biases[c];
        s_cumb[0] = acc;
        #pragma unroll
        for (int j = 1; j < NCP; j++) {
            acc = fmaf(s_slope[j], dt, acc);
            s_cumb[j] = acc;
        }
    }
    __syncthreads();

    if (tid < NSL) {
        const int i2 = max(tid - 1, 0);                 // [0, 32]
        const float cp = -1.0f + 0.0625f * (float)i2;   // left breakpoint
        const float a  = s_slope[tid];
        s_tab[tid] = make_float2(a, fmaf(-cp, a, s_cumb[i2]));
    }
    __syncthreads();

    const float4* __restrict__ xin = (const float4*)(x + (size_t)row * TLEN);
    float4* __restrict__ o         = (float4*)(out + (size_t)row * TLEN);

    // Phase 1: front-batched loads (MLP = 8 per thread)
    float4 v[VPT];
    #pragma unroll
    for (int i = 0; i < VPT; i++)
        v[i] = xin[tid + i * THREADS];

    // Phase 2: compute + store
    #pragma unroll
    for (int i = 0; i < VPT; i++) {
        float4 r;
        #pragma unroll
        for (int j = 0; j < 4; j++) {
            const float xv = (&v[i].x)[j];
            int i1 = __float2int_rd(fmaf(xv, 16.0f, 16.0f)) + 1;
            i1 = max(0, min(NCP, i1));          // [0, 33]
            const float2 ab = s_tab[i1];
            (&r.x)[j] = fmaf(xv, ab.x, ab.y);
        }
        o[tid + i * THREADS] = r;
    }
}

extern "C" void kernel_launch(void* const* d_in, const int* in_sizes, int n_in,
                              void* d_out, int out_size) {
    const float* x      = (const float*)d_in[0];
    const float* slopes = (const float*)d_in[1];
    const float* biases = (const float*)d_in[2];
    float* out          = (float*)d_out;

    const int rows = BATCH * CCH;  // 4096
    efficient_pwl_kernel<<<rows, THREADS>>>(x, slopes, biases, out);
}